// round 2
// baseline (speedup 1.0000x reference)
#include <cuda_runtime.h>

#define N_NODES 100000
#define N_EDGES 1600000
#define IN_CH 128
#define HID 32

// Scratch (device globals — no allocation allowed)
__device__ float g_bufA[N_NODES * HID];   // y, then t (gather source)
__device__ float g_bufB[N_NODES * HID];   // z1, then z2 (scatter destination)
__device__ float g_s[N_NODES];            // per-node scalar before final agg
__device__ float g_W12[HID * HID];        // w1b @ w2a
__device__ float g_c12[HID];              // b1b @ w2a
__device__ float g_W23[HID];              // w2b @ w3
__device__ float g_c23[1];                // b2b . w3
__device__ int   g_is64;                  // edge_index dtype flag (1 = int64)

// ---------------------------------------------------------------------------
// K_detect: figure out whether edge_index is int32 or int64.
// int64 little-endian => odd 32-bit words are high words of values < 2^31 => 0.
// int32 => odd words are random indices in [0, 100000) => all-zero impossible.
// ---------------------------------------------------------------------------
__global__ void k_detect(const int* __restrict__ ei_words) {
    int any = 0;
    #pragma unroll 8
    for (int i = 0; i < 256; i++) any |= ei_words[2 * i + 1];
    g_is64 = (any == 0) ? 1 : 0;
}

// ---------------------------------------------------------------------------
// K0: fold weights.  W12 = w1b@w2a, c12 = b1b@w2a, W23 = w2b@w3, c23 = b2b.w3
// ---------------------------------------------------------------------------
__global__ void k_precompute(const float* __restrict__ w1b, const float* __restrict__ b1b,
                             const float* __restrict__ w2a, const float* __restrict__ w2b,
                             const float* __restrict__ b2b, const float* __restrict__ w3) {
    int tid = threadIdx.x;
    {
        int i = tid >> 5, j = tid & 31;
        float acc = 0.f;
        #pragma unroll
        for (int k = 0; k < HID; k++) acc += w1b[i * HID + k] * w2a[k * HID + j];
        g_W12[i * HID + j] = acc;
    }
    if (tid < HID) {
        float acc = 0.f, acc2 = 0.f;
        #pragma unroll
        for (int k = 0; k < HID; k++) {
            acc  += b1b[k] * w2a[k * HID + tid];
            acc2 += w2b[tid * HID + k] * w3[k];
        }
        g_c12[tid] = acc;
        g_W23[tid] = acc2;
    }
    if (tid == 0) {
        float acc = 0.f;
        #pragma unroll
        for (int k = 0; k < HID; k++) acc += b2b[k] * w3[k];
        g_c23[0] = acc;
    }
}

// ---------------------------------------------------------------------------
// K1: y = x @ w1a   (100000x128 @ 128x32, fp32 FMA, weights in smem broadcast)
// also initializes z1 = y (self term of GIN aggregate)
// ---------------------------------------------------------------------------
__global__ void k_gemm1(const float* __restrict__ x, const float* __restrict__ w1a, int n) {
    __shared__ float ws[IN_CH * HID];
    for (int i = threadIdx.x; i < IN_CH * HID; i += blockDim.x) ws[i] = w1a[i];
    __syncthreads();

    int node = blockIdx.x * blockDim.x + threadIdx.x;
    if (node >= n) return;

    const float4* xr = (const float4*)(x + (size_t)node * IN_CH);
    float4 acc[8];
    #pragma unroll
    for (int j = 0; j < 8; j++) acc[j] = make_float4(0.f, 0.f, 0.f, 0.f);

    #pragma unroll 4
    for (int k4 = 0; k4 < IN_CH / 4; k4++) {
        float4 xv = __ldg(xr + k4);
        #pragma unroll
        for (int kk = 0; kk < 4; kk++) {
            float xk = (&xv.x)[kk];
            const float4* wr = (const float4*)(ws + (k4 * 4 + kk) * HID);
            #pragma unroll
            for (int j = 0; j < 8; j++) {
                float4 w = wr[j];
                acc[j].x += xk * w.x; acc[j].y += xk * w.y;
                acc[j].z += xk * w.z; acc[j].w += xk * w.w;
            }
        }
    }
    float4* ya = (float4*)(g_bufA + (size_t)node * HID);
    float4* zb = (float4*)(g_bufB + (size_t)node * HID);
    #pragma unroll
    for (int j = 0; j < 8; j++) { ya[j] = acc[j]; zb[j] = acc[j]; }
}

// ---------------------------------------------------------------------------
// Edge-index fetch helper (handles int32 or int64 storage)
// ---------------------------------------------------------------------------
__device__ __forceinline__ void load_edge(const void* ei, int idx, int e,
                                          int& sN, int& dN) {
    if (g_is64) {
        const long long* p = (const long long*)ei;
        sN = (int)__ldg(p + idx);
        dN = (int)__ldg(p + idx + e);
    } else {
        const int* p = (const int*)ei;
        sN = __ldg(p + idx);
        dN = __ldg(p + idx + e);
    }
}

// ---------------------------------------------------------------------------
// 32-channel edge scatter:  bufB[dst] += bufA[src]   (vector f32 L2 atomics)
// ---------------------------------------------------------------------------
__device__ __forceinline__ void red_add_v4(float* addr, float4 v) {
    asm volatile("red.global.add.v4.f32 [%0], {%1,%2,%3,%4};"
                 :: "l"(addr), "f"(v.x), "f"(v.y), "f"(v.z), "f"(v.w) : "memory");
}

__global__ void k_scatter32(const void* __restrict__ ei, int e) {
    int idx = blockIdx.x * blockDim.x + threadIdx.x;
    if (idx >= e) return;
    int sN, dN;
    load_edge(ei, idx, e, sN, dN);
    const float4* sp = (const float4*)(g_bufA + (size_t)sN * HID);
    float*        dp = g_bufB + (size_t)dN * HID;
    #pragma unroll
    for (int j = 0; j < 8; j++) {
        float4 v = __ldg(sp + j);
        red_add_v4(dp + j * 4, v);
    }
}

// ---------------------------------------------------------------------------
// K3: t = relu(z1 + b1a) @ W12 + c12 ; bufA = t ; bufB = t (self term)
// ---------------------------------------------------------------------------
__global__ void k_mlp_mid(const float* __restrict__ b1a, int n) {
    __shared__ float ws[HID * HID];
    __shared__ float sb[HID];
    __shared__ float sc[HID];
    for (int i = threadIdx.x; i < HID * HID; i += blockDim.x) ws[i] = g_W12[i];
    if (threadIdx.x < HID) { sb[threadIdx.x] = b1a[threadIdx.x]; sc[threadIdx.x] = g_c12[threadIdx.x]; }
    __syncthreads();

    int node = blockIdx.x * blockDim.x + threadIdx.x;
    if (node >= n) return;

    const float4* zr = (const float4*)(g_bufB + (size_t)node * HID);
    float v[HID];
    #pragma unroll
    for (int j = 0; j < 8; j++) {
        float4 z = __ldg(zr + j);
        v[j * 4 + 0] = fmaxf(z.x + sb[j * 4 + 0], 0.f);
        v[j * 4 + 1] = fmaxf(z.y + sb[j * 4 + 1], 0.f);
        v[j * 4 + 2] = fmaxf(z.z + sb[j * 4 + 2], 0.f);
        v[j * 4 + 3] = fmaxf(z.w + sb[j * 4 + 3], 0.f);
    }
    float4 acc[8];
    #pragma unroll
    for (int j = 0; j < 8; j++)
        acc[j] = make_float4(sc[j * 4 + 0], sc[j * 4 + 1], sc[j * 4 + 2], sc[j * 4 + 3]);
    #pragma unroll
    for (int k = 0; k < HID; k++) {
        float xk = v[k];
        const float4* wr = (const float4*)(ws + k * HID);
        #pragma unroll
        for (int j = 0; j < 8; j++) {
            float4 w = wr[j];
            acc[j].x += xk * w.x; acc[j].y += xk * w.y;
            acc[j].z += xk * w.z; acc[j].w += xk * w.w;
        }
    }
    float4* ta = (float4*)(g_bufA + (size_t)node * HID);
    float4* zb = (float4*)(g_bufB + (size_t)node * HID);
    #pragma unroll
    for (int j = 0; j < 8; j++) { ta[j] = acc[j]; zb[j] = acc[j]; }
}

// ---------------------------------------------------------------------------
// K5: s = relu(z2 + b2a) . W23 + c23 ;  g_s = s ; out = s + b3 (self term)
// ---------------------------------------------------------------------------
__global__ void k_final(const float* __restrict__ b2a, const float* __restrict__ b3,
                        float* __restrict__ out, int n) {
    __shared__ float w23[HID];
    __shared__ float sb[HID];
    if (threadIdx.x < HID) { w23[threadIdx.x] = g_W23[threadIdx.x]; sb[threadIdx.x] = b2a[threadIdx.x]; }
    __syncthreads();

    int node = blockIdx.x * blockDim.x + threadIdx.x;
    if (node >= n) return;

    const float4* zr = (const float4*)(g_bufB + (size_t)node * HID);
    float acc = g_c23[0];
    #pragma unroll
    for (int j = 0; j < 8; j++) {
        float4 z = __ldg(zr + j);
        acc += fmaxf(z.x + sb[j * 4 + 0], 0.f) * w23[j * 4 + 0];
        acc += fmaxf(z.y + sb[j * 4 + 1], 0.f) * w23[j * 4 + 1];
        acc += fmaxf(z.z + sb[j * 4 + 2], 0.f) * w23[j * 4 + 2];
        acc += fmaxf(z.w + sb[j * 4 + 3], 0.f) * w23[j * 4 + 3];
    }
    g_s[node] = acc;
    out[node] = acc + b3[0];
}

// ---------------------------------------------------------------------------
// K6: scalar edge scatter: out[dst] += g_s[src]
// ---------------------------------------------------------------------------
__global__ void k_scatter1(float* __restrict__ out, const void* __restrict__ ei, int e) {
    int idx = blockIdx.x * blockDim.x + threadIdx.x;
    if (idx >= e) return;
    int sN, dN;
    load_edge(ei, idx, e, sN, dN);
    atomicAdd(out + dN, __ldg(g_s + sN));
}

// ---------------------------------------------------------------------------
extern "C" void kernel_launch(void* const* d_in, const int* in_sizes, int n_in,
                              void* d_out, int out_size) {
    const float* x   = (const float*)d_in[0];
    const void*  ei  = d_in[1];
    const float* w1a = (const float*)d_in[2];
    const float* b1a = (const float*)d_in[3];
    const float* w1b = (const float*)d_in[4];
    const float* b1b = (const float*)d_in[5];
    const float* w2a = (const float*)d_in[6];
    const float* b2a = (const float*)d_in[7];
    const float* w2b = (const float*)d_in[8];
    const float* b2b = (const float*)d_in[9];
    const float* w3  = (const float*)d_in[10];
    const float* b3  = (const float*)d_in[11];

    int n = in_sizes[0] / IN_CH;       // 100000
    int e = in_sizes[1] / 2;           // 1600000
    float* out = (float*)d_out;

    int nb_n = (n + 255) / 256;
    int nb_e = (e + 255) / 256;

    k_detect<<<1, 1>>>((const int*)ei);
    k_precompute<<<1, 1024>>>(w1b, b1b, w2a, w2b, b2b, w3);
    k_gemm1<<<nb_n, 256>>>(x, w1a, n);           // y = x@w1a ; z1 = y
    k_scatter32<<<nb_e, 256>>>(ei, e);           // z1 += sum y[src]
    k_mlp_mid<<<nb_n, 256>>>(b1a, n);            // t = relu(z1+b1a)@W12+c12 ; z2 = t
    k_scatter32<<<nb_e, 256>>>(ei, e);           // z2 += sum t[src]
    k_final<<<nb_n, 256>>>(b2a, b3, out, n);     // s ; out = s + b3
    k_scatter1<<<nb_e, 256>>>(out, ei, e);       // out += sum s[src]
}

// round 3
// speedup vs baseline: 1.4930x; 1.4930x over previous
#include <cuda_runtime.h>

#define N_NODES 100000
#define N_EDGES 1600000
#define IN_CH 128
#define HID 32
#define SCAN_BLK 1024
#define NB_SCAN ((N_NODES + SCAN_BLK - 1) / SCAN_BLK)

// ---- scratch (device globals; no allocation allowed) ----
__device__ float g_y[N_NODES * HID];      // x@w1a
__device__ float g_t[N_NODES * HID];      // mid features
__device__ float g_s[N_NODES];            // pre-final scalars
__device__ float g_W12[HID * HID];        // w1b@w2a
__device__ float g_c12[HID];              // b1b@w2a
__device__ float g_W23[HID];              // w2b@w3
__device__ float g_c23[1];                // b2b.w3
__device__ int   g_is64;                  // edge dtype flag
__device__ int   g_deg[N_NODES];
__device__ int   g_rowptr[N_NODES + 1];
__device__ int   g_cursor[N_NODES];
__device__ int   g_col[N_EDGES];
__device__ int   g_bsum[NB_SCAN];

// ---------------------------------------------------------------------------
// detect int32 vs int64 edge_index (odd 32-bit words all zero => int64)
// ---------------------------------------------------------------------------
__global__ void k_detect(const int* __restrict__ ei_words) {
    int any = 0;
    #pragma unroll 8
    for (int i = 0; i < 256; i++) any |= ei_words[2 * i + 1];
    g_is64 = (any == 0) ? 1 : 0;
}

// ---------------------------------------------------------------------------
// fold weights: W12 = w1b@w2a, c12 = b1b@w2a, W23 = w2b@w3, c23 = b2b.w3
// ---------------------------------------------------------------------------
__global__ void k_precompute(const float* __restrict__ w1b, const float* __restrict__ b1b,
                             const float* __restrict__ w2a, const float* __restrict__ w2b,
                             const float* __restrict__ b2b, const float* __restrict__ w3) {
    int tid = threadIdx.x;
    {
        int i = tid >> 5, j = tid & 31;
        float acc = 0.f;
        #pragma unroll
        for (int k = 0; k < HID; k++) acc += w1b[i * HID + k] * w2a[k * HID + j];
        g_W12[i * HID + j] = acc;
    }
    if (tid < HID) {
        float acc = 0.f, acc2 = 0.f;
        #pragma unroll
        for (int k = 0; k < HID; k++) {
            acc  += b1b[k] * w2a[k * HID + tid];
            acc2 += w2b[tid * HID + k] * w3[k];
        }
        g_c12[tid] = acc;
        g_W23[tid] = acc2;
    }
    if (tid == 0) {
        float acc = 0.f;
        #pragma unroll
        for (int k = 0; k < HID; k++) acc += b2b[k] * w3[k];
        g_c23[0] = acc;
    }
}

// ---------------------------------------------------------------------------
// CSR build: zero -> histogram(dst) -> 2-level exclusive scan -> fill cols
// ---------------------------------------------------------------------------
__global__ void k_zero() {
    int i = blockIdx.x * blockDim.x + threadIdx.x;
    if (i < N_NODES) g_deg[i] = 0;
}

__global__ void k_hist(const void* __restrict__ ei, int e) {
    int i = blockIdx.x * blockDim.x + threadIdx.x;
    if (i >= e) return;
    int d = g_is64 ? (int)__ldg((const long long*)ei + i + e)
                   : __ldg((const int*)ei + i + e);
    atomicAdd(&g_deg[d], 1);
}

__global__ void k_scan1() {
    __shared__ int sw[32];
    int i = blockIdx.x * SCAN_BLK + threadIdx.x;
    int lane = threadIdx.x & 31, wid = threadIdx.x >> 5;
    int v = (i < N_NODES) ? g_deg[i] : 0;
    int inc = v;
    #pragma unroll
    for (int d = 1; d < 32; d <<= 1) {
        int t = __shfl_up_sync(0xffffffffu, inc, d);
        if (lane >= d) inc += t;
    }
    if (lane == 31) sw[wid] = inc;
    __syncthreads();
    if (wid == 0) {
        int wv = sw[lane];
        #pragma unroll
        for (int d = 1; d < 32; d <<= 1) {
            int t = __shfl_up_sync(0xffffffffu, wv, d);
            if (lane >= d) wv += t;
        }
        sw[lane] = wv;
    }
    __syncthreads();
    int off = (wid > 0) ? sw[wid - 1] : 0;
    if (i < N_NODES) g_rowptr[i] = off + inc - v;
    if (threadIdx.x == SCAN_BLK - 1) g_bsum[blockIdx.x] = sw[31];
}

__global__ void k_scan2() {
    __shared__ int s[128];
    int tid = threadIdx.x;
    s[tid] = (tid < NB_SCAN) ? g_bsum[tid] : 0;
    __syncthreads();
    for (int d = 1; d < 128; d <<= 1) {
        int t = (tid >= d) ? s[tid - d] : 0;
        __syncthreads();
        s[tid] += t;
        __syncthreads();
    }
    if (tid < NB_SCAN) g_bsum[tid] = (tid > 0) ? s[tid - 1] : 0;
    if (tid == 0) g_rowptr[N_NODES] = N_EDGES;
}

__global__ void k_scan3() {
    int i = blockIdx.x * blockDim.x + threadIdx.x;
    if (i >= N_NODES) return;
    int r = g_rowptr[i] + g_bsum[i / SCAN_BLK];
    g_rowptr[i] = r;
    g_cursor[i] = r;
}

__global__ void k_fill(const void* __restrict__ ei, int e) {
    int i = blockIdx.x * blockDim.x + threadIdx.x;
    if (i >= e) return;
    int sN, dN;
    if (g_is64) {
        sN = (int)__ldg((const long long*)ei + i);
        dN = (int)__ldg((const long long*)ei + i + e);
    } else {
        sN = __ldg((const int*)ei + i);
        dN = __ldg((const int*)ei + i + e);
    }
    int p = atomicAdd(&g_cursor[dN], 1);
    g_col[p] = sN;
}

// ---------------------------------------------------------------------------
// gemm1: y = x @ w1a, smem-staged for coalescing (32 nodes/block, 128 thr)
// ---------------------------------------------------------------------------
#define G1_NODES 32
#define G1_THREADS 128
#define XPAD 132

__global__ __launch_bounds__(G1_THREADS)
void k_gemm1(const float* __restrict__ x, const float* __restrict__ w1a, int n) {
    __shared__ float xs[G1_NODES * XPAD];
    __shared__ float ws[IN_CH * HID];
    int tid = threadIdx.x;
    for (int idx = tid; idx < IN_CH * HID / 4; idx += G1_THREADS)
        ((float4*)ws)[idx] = __ldg((const float4*)w1a + idx);
    int nb = blockIdx.x * G1_NODES;
    for (int idx = tid; idx < G1_NODES * (IN_CH / 4); idx += G1_THREADS) {
        int node = idx >> 5, f4 = idx & 31;
        float4 v = (nb + node < n)
            ? __ldg((const float4*)(x + (size_t)(nb + node) * IN_CH) + f4)
            : make_float4(0.f, 0.f, 0.f, 0.f);
        *((float4*)(xs + node * XPAD + f4 * 4)) = v;
    }
    __syncthreads();

    int nl = tid >> 2;
    int jg = (tid & 3) * 8;
    int node = nb + nl;
    float4 a0 = make_float4(0.f, 0.f, 0.f, 0.f);
    float4 a1 = make_float4(0.f, 0.f, 0.f, 0.f);
    const float* xr = xs + nl * XPAD;
    #pragma unroll 8
    for (int k = 0; k < IN_CH; k++) {
        float xk = xr[k];
        float4 w0 = *((const float4*)(ws + k * HID + jg));
        float4 w1 = *((const float4*)(ws + k * HID + jg + 4));
        a0.x += xk * w0.x; a0.y += xk * w0.y; a0.z += xk * w0.z; a0.w += xk * w0.w;
        a1.x += xk * w1.x; a1.y += xk * w1.y; a1.z += xk * w1.z; a1.w += xk * w1.w;
    }
    if (node < n) {
        float4* yr = (float4*)(g_y + (size_t)node * HID + jg);
        yr[0] = a0; yr[1] = a1;
    }
}

// ---------------------------------------------------------------------------
// gather (warp/node) + fused mid-MLP: t = relu(z1+b1a)@W12 + c12
// ---------------------------------------------------------------------------
__global__ void k_gather_mlp(const float* __restrict__ b1a, int n) {
    __shared__ float ws[HID * HID];
    __shared__ float sb[HID];
    __shared__ float sc[HID];
    int tid = threadIdx.x;
    for (int i2 = tid; i2 < HID * HID; i2 += blockDim.x) ws[i2] = g_W12[i2];
    if (tid < HID) { sb[tid] = b1a[tid]; sc[tid] = g_c12[tid]; }
    __syncthreads();

    int warp = (blockIdx.x * blockDim.x + tid) >> 5;
    int lane = tid & 31;
    if (warp >= n) return;
    int beg = g_rowptr[warp], end = g_rowptr[warp + 1];
    float acc = g_y[(size_t)warp * HID + lane];
    int k = beg;
    for (; k + 4 <= end; k += 4) {
        int s0 = __ldg(g_col + k),     s1 = __ldg(g_col + k + 1);
        int s2 = __ldg(g_col + k + 2), s3 = __ldg(g_col + k + 3);
        acc += __ldg(g_y + (size_t)s0 * HID + lane) + __ldg(g_y + (size_t)s1 * HID + lane)
             + __ldg(g_y + (size_t)s2 * HID + lane) + __ldg(g_y + (size_t)s3 * HID + lane);
    }
    for (; k < end; k++)
        acc += __ldg(g_y + (size_t)__ldg(g_col + k) * HID + lane);

    float v = fmaxf(acc + sb[lane], 0.f);
    float acc2 = sc[lane];
    #pragma unroll
    for (int kk = 0; kk < HID; kk++)
        acc2 = fmaf(__shfl_sync(0xffffffffu, v, kk), ws[kk * HID + lane], acc2);
    g_t[(size_t)warp * HID + lane] = acc2;
}

// ---------------------------------------------------------------------------
// gather (warp/node) + fused final scalar: s = relu(z2+b2a).W23 + c23
// ---------------------------------------------------------------------------
__global__ void k_gather_final(const float* __restrict__ b2a, int n) {
    __shared__ float w23[HID];
    __shared__ float sb[HID];
    int tid = threadIdx.x;
    if (tid < HID) { w23[tid] = g_W23[tid]; sb[tid] = b2a[tid]; }
    __syncthreads();

    int warp = (blockIdx.x * blockDim.x + tid) >> 5;
    int lane = tid & 31;
    if (warp >= n) return;
    int beg = g_rowptr[warp], end = g_rowptr[warp + 1];
    float acc = g_t[(size_t)warp * HID + lane];
    int k = beg;
    for (; k + 4 <= end; k += 4) {
        int s0 = __ldg(g_col + k),     s1 = __ldg(g_col + k + 1);
        int s2 = __ldg(g_col + k + 2), s3 = __ldg(g_col + k + 3);
        acc += __ldg(g_t + (size_t)s0 * HID + lane) + __ldg(g_t + (size_t)s1 * HID + lane)
             + __ldg(g_t + (size_t)s2 * HID + lane) + __ldg(g_t + (size_t)s3 * HID + lane);
    }
    for (; k < end; k++)
        acc += __ldg(g_t + (size_t)__ldg(g_col + k) * HID + lane);

    float v = fmaxf(acc + sb[lane], 0.f) * w23[lane];
    #pragma unroll
    for (int o = 16; o; o >>= 1) v += __shfl_xor_sync(0xffffffffu, v, o);
    if (lane == 0) g_s[warp] = v + g_c23[0];
}

// ---------------------------------------------------------------------------
// final scalar gather: out = s_self + sum s[src] + b3
// ---------------------------------------------------------------------------
__global__ void k_gather_out(const float* __restrict__ b3, float* __restrict__ out, int n) {
    int tid = threadIdx.x;
    int warp = (blockIdx.x * blockDim.x + tid) >> 5;
    int lane = tid & 31;
    if (warp >= n) return;
    int beg = g_rowptr[warp], end = g_rowptr[warp + 1];
    float acc = 0.f;
    for (int k = beg + lane; k < end; k += 32)
        acc += __ldg(g_s + __ldg(g_col + k));
    #pragma unroll
    for (int o = 16; o; o >>= 1) acc += __shfl_xor_sync(0xffffffffu, acc, o);
    if (lane == 0) out[warp] = acc + g_s[warp] + b3[0];
}

// ---------------------------------------------------------------------------
extern "C" void kernel_launch(void* const* d_in, const int* in_sizes, int n_in,
                              void* d_out, int out_size) {
    const float* x   = (const float*)d_in[0];
    const void*  ei  = d_in[1];
    const float* w1a = (const float*)d_in[2];
    const float* b1a = (const float*)d_in[3];
    const float* w1b = (const float*)d_in[4];
    const float* b1b = (const float*)d_in[5];
    const float* w2a = (const float*)d_in[6];
    const float* b2a = (const float*)d_in[7];
    const float* w2b = (const float*)d_in[8];
    const float* b2b = (const float*)d_in[9];
    const float* w3  = (const float*)d_in[10];
    const float* b3  = (const float*)d_in[11];

    int n = in_sizes[0] / IN_CH;   // 100000
    int e = in_sizes[1] / 2;       // 1600000
    float* out = (float*)d_out;

    int nb_e = (e + 255) / 256;
    int nb_w = (n * 32 + 255) / 256;   // warp-per-node grids

    k_detect<<<1, 1>>>((const int*)ei);
    k_precompute<<<1, 1024>>>(w1b, b1b, w2a, w2b, b2b, w3);

    // CSR build
    k_zero<<<(N_NODES + 1023) / 1024, 1024>>>();
    k_hist<<<nb_e, 256>>>(ei, e);
    k_scan1<<<NB_SCAN, SCAN_BLK>>>();
    k_scan2<<<1, 128>>>();
    k_scan3<<<(N_NODES + 255) / 256, 256>>>();
    k_fill<<<nb_e, 256>>>(ei, e);

    // pipeline
    k_gemm1<<<(n + G1_NODES - 1) / G1_NODES, G1_THREADS>>>(x, w1a, n);
    k_gather_mlp<<<nb_w, 256>>>(b1a, n);
    k_gather_final<<<nb_w, 256>>>(b2a, n);
    k_gather_out<<<nb_w, 256>>>(b3, out, n);
}

// round 4
// speedup vs baseline: 1.5187x; 1.0172x over previous
#include <cuda_runtime.h>
#include <cuda_fp16.h>

#define N_NODES 100000
#define N_EDGES 1600000
#define IN_CH 128
#define HID 32
#define SCAN_BLK 1024
#define NB_SCAN ((N_NODES + SCAN_BLK - 1) / SCAN_BLK)

// ---- scratch (device globals; no allocation allowed) ----
__device__ __half g_y[N_NODES * HID];     // x@w1a   (fp16 storage, fp32 math)
__device__ __half g_t[N_NODES * HID];     // mid features
__device__ float  g_s[N_NODES];           // pre-final scalars
__device__ float  g_W12[HID * HID];       // w1b@w2a
__device__ float  g_c12[HID];             // b1b@w2a
__device__ float  g_W23[HID];             // w2b@w3
__device__ float  g_c23[1];               // b2b.w3
__device__ int    g_is64;                 // edge dtype flag
__device__ int    g_rowptr[N_NODES + 1];  // also used as degree before scan
__device__ int    g_deg[N_NODES];
__device__ int    g_cursor[N_NODES];
__device__ int    g_col[N_EDGES];
__device__ int    g_bsum[NB_SCAN];

// ---------------------------------------------------------------------------
// k_init: zero degree array; block 0 additionally detects edge dtype and
// folds the weights (W12 = w1b@w2a, c12 = b1b@w2a, W23 = w2b@w3, c23 = b2b.w3)
// ---------------------------------------------------------------------------
__global__ void k_init(const int* __restrict__ ei_words,
                       const float* __restrict__ w1b, const float* __restrict__ b1b,
                       const float* __restrict__ w2a, const float* __restrict__ w2b,
                       const float* __restrict__ b2b, const float* __restrict__ w3) {
    int i = blockIdx.x * blockDim.x + threadIdx.x;
    if (i < N_NODES) g_deg[i] = 0;
    if (blockIdx.x != 0) return;
    int tid = threadIdx.x;
    if (tid == 0) {
        // int64 little-endian => odd 32-bit words are high words of small values => 0
        int any = 0;
        #pragma unroll 8
        for (int q = 0; q < 256; q++) any |= ei_words[2 * q + 1];
        g_is64 = (any == 0) ? 1 : 0;
    }
    {
        int r = tid >> 5, c = tid & 31;
        float acc = 0.f;
        #pragma unroll
        for (int k = 0; k < HID; k++) acc += w1b[r * HID + k] * w2a[k * HID + c];
        g_W12[r * HID + c] = acc;
    }
    if (tid < HID) {
        float acc = 0.f, acc2 = 0.f;
        #pragma unroll
        for (int k = 0; k < HID; k++) {
            acc  += b1b[k] * w2a[k * HID + tid];
            acc2 += w2b[tid * HID + k] * w3[k];
        }
        g_c12[tid] = acc;
        g_W23[tid] = acc2;
    }
    if (tid == 0) {
        float acc = 0.f;
        #pragma unroll
        for (int k = 0; k < HID; k++) acc += b2b[k] * w3[k];
        g_c23[0] = acc;
    }
}

// ---------------------------------------------------------------------------
// histogram of dst (4 edges / thread, vectorized loads)
// ---------------------------------------------------------------------------
__global__ void k_hist(const void* __restrict__ ei, int e) {
    int i4 = (blockIdx.x * blockDim.x + threadIdx.x) * 4;
    if (i4 >= e) return;
    if (i4 + 4 <= e) {
        if (g_is64) {
            const long long* p = (const long long*)ei + e + i4;
            longlong2 a = __ldg((const longlong2*)p);
            longlong2 b = __ldg((const longlong2*)(p + 2));
            atomicAdd(&g_deg[(int)a.x], 1); atomicAdd(&g_deg[(int)a.y], 1);
            atomicAdd(&g_deg[(int)b.x], 1); atomicAdd(&g_deg[(int)b.y], 1);
        } else {
            int4 d = __ldg((const int4*)((const int*)ei + e + i4));
            atomicAdd(&g_deg[d.x], 1); atomicAdd(&g_deg[d.y], 1);
            atomicAdd(&g_deg[d.z], 1); atomicAdd(&g_deg[d.w], 1);
        }
    } else {
        for (int i = i4; i < e; i++) {
            int d = g_is64 ? (int)__ldg((const long long*)ei + e + i)
                           : __ldg((const int*)ei + e + i);
            atomicAdd(&g_deg[d], 1);
        }
    }
}

// ---------------------------------------------------------------------------
// scan1: per-block (1024) exclusive scan of degrees -> rowptr (local), bsum
// ---------------------------------------------------------------------------
__global__ void k_scan1() {
    __shared__ int sw[32];
    int i = blockIdx.x * SCAN_BLK + threadIdx.x;
    int lane = threadIdx.x & 31, wid = threadIdx.x >> 5;
    int v = (i < N_NODES) ? g_deg[i] : 0;
    int inc = v;
    #pragma unroll
    for (int d = 1; d < 32; d <<= 1) {
        int t = __shfl_up_sync(0xffffffffu, inc, d);
        if (lane >= d) inc += t;
    }
    if (lane == 31) sw[wid] = inc;
    __syncthreads();
    if (wid == 0) {
        int wv = sw[lane];
        #pragma unroll
        for (int d = 1; d < 32; d <<= 1) {
            int t = __shfl_up_sync(0xffffffffu, wv, d);
            if (lane >= d) wv += t;
        }
        sw[lane] = wv;
    }
    __syncthreads();
    int off = (wid > 0) ? sw[wid - 1] : 0;
    if (i < N_NODES) g_rowptr[i] = off + inc - v;
    if (threadIdx.x == SCAN_BLK - 1) g_bsum[blockIdx.x] = sw[31];
}

// ---------------------------------------------------------------------------
// scan3: every block re-scans the 98 block sums in smem, adds prefix,
// writes final rowptr + cursor
// ---------------------------------------------------------------------------
__global__ void k_scan3(int e) {
    __shared__ int s[128];
    int t = threadIdx.x;
    if (t < 128) s[t] = (t < NB_SCAN) ? g_bsum[t] : 0;
    __syncthreads();
    for (int d = 1; d < 128; d <<= 1) {
        int v = 0;
        if (t >= d && t < 128) v = s[t - d];
        __syncthreads();
        if (t < 128) s[t] += v;
        __syncthreads();
    }
    int i = blockIdx.x * blockDim.x + t;
    if (i < N_NODES) {
        int b = i / SCAN_BLK;
        int add = b ? s[b - 1] : 0;
        int r = g_rowptr[i] + add;
        g_rowptr[i] = r;
        g_cursor[i] = r;
    }
    if (i == 0) g_rowptr[N_NODES] = e;
}

// ---------------------------------------------------------------------------
// fill: bucket src by dst (4 edges / thread)
// ---------------------------------------------------------------------------
__global__ void k_fill(const void* __restrict__ ei, int e) {
    int i4 = (blockIdx.x * blockDim.x + threadIdx.x) * 4;
    if (i4 >= e) return;
    int s0, s1, s2, s3, d0, d1, d2, d3;
    if (i4 + 4 <= e) {
        if (g_is64) {
            const long long* ps = (const long long*)ei + i4;
            const long long* pd = (const long long*)ei + e + i4;
            longlong2 sa = __ldg((const longlong2*)ps);
            longlong2 sb = __ldg((const longlong2*)(ps + 2));
            longlong2 da = __ldg((const longlong2*)pd);
            longlong2 db = __ldg((const longlong2*)(pd + 2));
            s0 = (int)sa.x; s1 = (int)sa.y; s2 = (int)sb.x; s3 = (int)sb.y;
            d0 = (int)da.x; d1 = (int)da.y; d2 = (int)db.x; d3 = (int)db.y;
        } else {
            int4 sv = __ldg((const int4*)((const int*)ei + i4));
            int4 dv = __ldg((const int4*)((const int*)ei + e + i4));
            s0 = sv.x; s1 = sv.y; s2 = sv.z; s3 = sv.w;
            d0 = dv.x; d1 = dv.y; d2 = dv.z; d3 = dv.w;
        }
        g_col[atomicAdd(&g_cursor[d0], 1)] = s0;
        g_col[atomicAdd(&g_cursor[d1], 1)] = s1;
        g_col[atomicAdd(&g_cursor[d2], 1)] = s2;
        g_col[atomicAdd(&g_cursor[d3], 1)] = s3;
    } else {
        for (int i = i4; i < e; i++) {
            int sN, dN;
            if (g_is64) {
                sN = (int)__ldg((const long long*)ei + i);
                dN = (int)__ldg((const long long*)ei + i + e);
            } else {
                sN = __ldg((const int*)ei + i);
                dN = __ldg((const int*)ei + i + e);
            }
            g_col[atomicAdd(&g_cursor[dN], 1)] = sN;
        }
    }
}

// ---------------------------------------------------------------------------
// gemm1: y = x @ w1a (fp16 out), smem-staged for coalescing
// ---------------------------------------------------------------------------
#define G1_NODES 32
#define G1_THREADS 128
#define XPAD 132

__global__ __launch_bounds__(G1_THREADS)
void k_gemm1(const float* __restrict__ x, const float* __restrict__ w1a, int n) {
    __shared__ float xs[G1_NODES * XPAD];
    __shared__ float ws[IN_CH * HID];
    int tid = threadIdx.x;
    for (int idx = tid; idx < IN_CH * HID / 4; idx += G1_THREADS)
        ((float4*)ws)[idx] = __ldg((const float4*)w1a + idx);
    int nb = blockIdx.x * G1_NODES;
    for (int idx = tid; idx < G1_NODES * (IN_CH / 4); idx += G1_THREADS) {
        int node = idx >> 5, f4 = idx & 31;
        float4 v = (nb + node < n)
            ? __ldg((const float4*)(x + (size_t)(nb + node) * IN_CH) + f4)
            : make_float4(0.f, 0.f, 0.f, 0.f);
        *((float4*)(xs + node * XPAD + f4 * 4)) = v;
    }
    __syncthreads();

    int nl = tid >> 2;
    int jg = (tid & 3) * 8;
    int node = nb + nl;
    float4 a0 = make_float4(0.f, 0.f, 0.f, 0.f);
    float4 a1 = make_float4(0.f, 0.f, 0.f, 0.f);
    const float* xr = xs + nl * XPAD;
    #pragma unroll 8
    for (int k = 0; k < IN_CH; k++) {
        float xk = xr[k];
        float4 w0 = *((const float4*)(ws + k * HID + jg));
        float4 w1 = *((const float4*)(ws + k * HID + jg + 4));
        a0.x += xk * w0.x; a0.y += xk * w0.y; a0.z += xk * w0.z; a0.w += xk * w0.w;
        a1.x += xk * w1.x; a1.y += xk * w1.y; a1.z += xk * w1.z; a1.w += xk * w1.w;
    }
    if (node < n) {
        __half2 h0 = __floats2half2_rn(a0.x, a0.y);
        __half2 h1 = __floats2half2_rn(a0.z, a0.w);
        __half2 h2 = __floats2half2_rn(a1.x, a1.y);
        __half2 h3 = __floats2half2_rn(a1.z, a1.w);
        uint4 u;
        u.x = *(unsigned*)&h0; u.y = *(unsigned*)&h1;
        u.z = *(unsigned*)&h2; u.w = *(unsigned*)&h3;
        *((uint4*)(g_y + (size_t)node * HID + jg)) = u;
    }
}

// ---------------------------------------------------------------------------
// gather (warp/node) + fused mid-MLP: t = relu(z1+b1a)@W12 + c12  (fp16 out)
// ---------------------------------------------------------------------------
__global__ void k_gather_mlp(const float* __restrict__ b1a, int n) {
    __shared__ float ws[HID * HID];
    __shared__ float sb[HID];
    __shared__ float sc[HID];
    int tid = threadIdx.x;
    for (int i2 = tid; i2 < HID * HID; i2 += blockDim.x) ws[i2] = g_W12[i2];
    if (tid < HID) { sb[tid] = b1a[tid]; sc[tid] = g_c12[tid]; }
    __syncthreads();

    int warp = (blockIdx.x * blockDim.x + tid) >> 5;
    int lane = tid & 31;
    if (warp >= n) return;
    int beg = g_rowptr[warp], end = g_rowptr[warp + 1];
    float acc = __half2float(g_y[(size_t)warp * HID + lane]);
    int k = beg;
    for (; k + 4 <= end; k += 4) {
        int s0 = __ldg(g_col + k),     s1 = __ldg(g_col + k + 1);
        int s2 = __ldg(g_col + k + 2), s3 = __ldg(g_col + k + 3);
        acc += __half2float(__ldg(g_y + (size_t)s0 * HID + lane))
             + __half2float(__ldg(g_y + (size_t)s1 * HID + lane))
             + __half2float(__ldg(g_y + (size_t)s2 * HID + lane))
             + __half2float(__ldg(g_y + (size_t)s3 * HID + lane));
    }
    for (; k < end; k++)
        acc += __half2float(__ldg(g_y + (size_t)__ldg(g_col + k) * HID + lane));

    float v = fmaxf(acc + sb[lane], 0.f);
    float acc2 = sc[lane];
    #pragma unroll
    for (int kk = 0; kk < HID; kk++)
        acc2 = fmaf(__shfl_sync(0xffffffffu, v, kk), ws[kk * HID + lane], acc2);
    g_t[(size_t)warp * HID + lane] = __float2half_rn(acc2);
}

// ---------------------------------------------------------------------------
// gather (warp/node) + fused final scalar: s = relu(z2+b2a).W23 + c23
// ---------------------------------------------------------------------------
__global__ void k_gather_final(const float* __restrict__ b2a, int n) {
    __shared__ float w23[HID];
    __shared__ float sb[HID];
    int tid = threadIdx.x;
    if (tid < HID) { w23[tid] = g_W23[tid]; sb[tid] = b2a[tid]; }
    __syncthreads();

    int warp = (blockIdx.x * blockDim.x + tid) >> 5;
    int lane = tid & 31;
    if (warp >= n) return;
    int beg = g_rowptr[warp], end = g_rowptr[warp + 1];
    float acc = __half2float(g_t[(size_t)warp * HID + lane]);
    int k = beg;
    for (; k + 4 <= end; k += 4) {
        int s0 = __ldg(g_col + k),     s1 = __ldg(g_col + k + 1);
        int s2 = __ldg(g_col + k + 2), s3 = __ldg(g_col + k + 3);
        acc += __half2float(__ldg(g_t + (size_t)s0 * HID + lane))
             + __half2float(__ldg(g_t + (size_t)s1 * HID + lane))
             + __half2float(__ldg(g_t + (size_t)s2 * HID + lane))
             + __half2float(__ldg(g_t + (size_t)s3 * HID + lane));
    }
    for (; k < end; k++)
        acc += __half2float(__ldg(g_t + (size_t)__ldg(g_col + k) * HID + lane));

    float v = fmaxf(acc + sb[lane], 0.f) * w23[lane];
    #pragma unroll
    for (int o = 16; o; o >>= 1) v += __shfl_xor_sync(0xffffffffu, v, o);
    if (lane == 0) g_s[warp] = v + g_c23[0];
}

// ---------------------------------------------------------------------------
// final scalar gather: out = s_self + sum s[src] + b3
// ---------------------------------------------------------------------------
__global__ void k_gather_out(const float* __restrict__ b3, float* __restrict__ out, int n) {
    int tid = threadIdx.x;
    int warp = (blockIdx.x * blockDim.x + tid) >> 5;
    int lane = tid & 31;
    if (warp >= n) return;
    int beg = g_rowptr[warp], end = g_rowptr[warp + 1];
    float acc = 0.f;
    for (int k = beg + lane; k < end; k += 32)
        acc += __ldg(g_s + __ldg(g_col + k));
    #pragma unroll
    for (int o = 16; o; o >>= 1) acc += __shfl_xor_sync(0xffffffffu, acc, o);
    if (lane == 0) out[warp] = acc + g_s[warp] + b3[0];
}

// ---------------------------------------------------------------------------
extern "C" void kernel_launch(void* const* d_in, const int* in_sizes, int n_in,
                              void* d_out, int out_size) {
    const float* x   = (const float*)d_in[0];
    const void*  ei  = d_in[1];
    const float* w1a = (const float*)d_in[2];
    const float* b1a = (const float*)d_in[3];
    const float* w1b = (const float*)d_in[4];
    const float* b1b = (const float*)d_in[5];
    const float* w2a = (const float*)d_in[6];
    const float* b2a = (const float*)d_in[7];
    const float* w2b = (const float*)d_in[8];
    const float* b2b = (const float*)d_in[9];
    const float* w3  = (const float*)d_in[10];
    const float* b3  = (const float*)d_in[11];

    int n = in_sizes[0] / IN_CH;   // 100000
    int e = in_sizes[1] / 2;       // 1600000
    float* out = (float*)d_out;

    int nb_e4 = (e / 4 + 255) / 256 + 1;
    int nb_w  = (n * 32 + 255) / 256;   // warp-per-node grids

    k_init<<<NB_SCAN, SCAN_BLK>>>((const int*)ei, w1b, b1b, w2a, w2b, b2b, w3);
    k_hist<<<nb_e4, 256>>>(ei, e);
    k_scan1<<<NB_SCAN, SCAN_BLK>>>();
    k_scan3<<<(N_NODES + 255) / 256, 256>>>(e);
    k_fill<<<nb_e4, 256>>>(ei, e);

    k_gemm1<<<(n + G1_NODES - 1) / G1_NODES, G1_THREADS>>>(x, w1a, n);
    k_gather_mlp<<<nb_w, 256>>>(b1a, n);
    k_gather_final<<<nb_w, 256>>>(b2a, n);
    k_gather_out<<<nb_w, 256>>>(b3, out, n);
}